// round 12
// baseline (speedup 1.0000x reference)
#include <cuda_runtime.h>
#include <cuda_bf16.h>
#include <cstdint>

// ---------------- problem constants (B=2, S=4096, D=2048) ----------------
constexpr int Bb = 2, Sq = 4096, Dd = 2048;
constexpr int Mrows = Bb * Sq;                    // 8192 GEMM rows
constexpr size_t NTOT = (size_t)Bb * Sq * Dd;     // 16,777,216
constexpr int NCHUNK = 64, TCH = Sq / NCHUNK, CHAN = Bb * Dd;

// ---------------- GEMM tiling ----------------
constexpr int BM = 128, BN = 128, BKT = 32;       // CTA tile
constexpr int KTILES = Dd / BKT;                  // 64
constexpr int NST = 3;                            // pipeline stages
constexpr int LDS_PAD = 36;                       // floats per smem row (32 + 4 pad)
constexpr int TILE_FLOATS = 128 * LDS_PAD;        // per A or B tile
constexpr int DSMEM_BYTES = NST * 2 * TILE_FLOATS * 4;  // 110,592 B

// ---------------- scratch (device globals; allocation-free) ----------------
__device__ float g_gate[(size_t)Mrows * Dd];      // tf32-rounded gate
__device__ float g_WT[2ull * Dd * Dd];            // [4096][2048] K-major: WaT ; WbT (tf32)
__device__ float g_alphas[(size_t)Mrows * Dd];
__device__ float g_betas[(size_t)Mrows * Dd];
__device__ float g_Ac[NCHUNK * CHAN], g_Hc[NCHUNK * CHAN], g_carry[NCHUNK * CHAN];

// ================= helpers =================
__device__ __forceinline__ uint32_t smem_u32(const void* p) {
    uint32_t a;
    asm("{ .reg .u64 t; cvta.to.shared.u64 t, %1; cvt.u32.u64 %0, t; }" : "=r"(a) : "l"(p));
    return a;
}
__device__ __forceinline__ float tf32r(float x) {
    uint32_t r;
    asm("cvt.rna.tf32.f32 %0, %1;" : "=r"(r) : "f"(x));
    return __uint_as_float(r);
}
__device__ __forceinline__ void cp_async16(uint32_t saddr, const void* gaddr) {
    asm volatile("cp.async.cg.shared.global [%0], [%1], 16;" :: "r"(saddr), "l"(gaddr));
}
#define CP_COMMIT() asm volatile("cp.async.commit_group;" ::: "memory")
#define CP_WAIT1()  asm volatile("cp.async.wait_group 1;" ::: "memory")

__device__ __forceinline__ void ldsm_x4(uint32_t& r0, uint32_t& r1, uint32_t& r2, uint32_t& r3,
                                        uint32_t addr) {
    asm volatile("ldmatrix.sync.aligned.m8n8.x4.shared.b16 {%0,%1,%2,%3}, [%4];"
                 : "=r"(r0), "=r"(r1), "=r"(r2), "=r"(r3) : "r"(addr));
}

__device__ __forceinline__ void mma_tf32_16n8k8(float& d0, float& d1, float& d2, float& d3,
                                                uint32_t a0, uint32_t a1, uint32_t a2, uint32_t a3,
                                                uint32_t b0, uint32_t b1) {
    asm volatile(
        "mma.sync.aligned.m16n8k8.row.col.f32.tf32.tf32.f32 "
        "{%0,%1,%2,%3}, {%4,%5,%6,%7}, {%8,%9}, {%0,%1,%2,%3};"
        : "+f"(d0), "+f"(d1), "+f"(d2), "+f"(d3)
        : "r"(a0), "r"(a1), "r"(a2), "r"(a3), "r"(b0), "r"(b1));
}

// ============================================================
// K0: W[K,N] -> WT[N,K] with tf32 rounding. grid (64,64,2), block (32,8)
// ============================================================
__global__ __launch_bounds__(256)
void transpose_w_kernel(const float* __restrict__ Wa, const float* __restrict__ Wb)
{
    __shared__ float t[32][33];
    const int w = blockIdx.z;
    const float* __restrict__ W = w ? Wb : Wa;
    const int bn = blockIdx.x * 32;
    const int bk = blockIdx.y * 32;
    const int tx = threadIdx.x, ty = threadIdx.y;

#pragma unroll
    for (int i = ty; i < 32; i += 8)
        t[i][tx] = W[(size_t)(bk + i) * Dd + bn + tx];
    __syncthreads();
#pragma unroll
    for (int i = ty; i < 32; i += 8)
        g_WT[(size_t)(w * Dd + bn + i) * Dd + bk + tx] = tf32r(t[tx][i]);
}

// ============================================================
// K1: gate = rms_norm(c) + rms_norm(prev_fetched) (tf32-rounded), c passthrough
// ============================================================
__global__ __launch_bounds__(256)
void rms_gate_kernel(const float* __restrict__ c,
                     const float* __restrict__ pf,
                     float* __restrict__ c_out)
{
    const int row = blockIdx.x;
    const size_t base = (size_t)row * Dd;
    const int tid = threadIdx.x;

    const float4* c4 = (const float4*)(c + base);
    const float4* p4 = (const float4*)(pf + base);

    float4 cv[2], pv[2];
    float sc = 0.f, sp = 0.f;
#pragma unroll
    for (int i = 0; i < 2; i++) {
        cv[i] = c4[tid + i * 256];
        pv[i] = p4[tid + i * 256];
        sc += cv[i].x * cv[i].x + cv[i].y * cv[i].y + cv[i].z * cv[i].z + cv[i].w * cv[i].w;
        sp += pv[i].x * pv[i].x + pv[i].y * pv[i].y + pv[i].z * pv[i].z + pv[i].w * pv[i].w;
    }
#pragma unroll
    for (int o = 16; o > 0; o >>= 1) {
        sc += __shfl_xor_sync(0xFFFFFFFFu, sc, o);
        sp += __shfl_xor_sync(0xFFFFFFFFu, sp, o);
    }
    __shared__ float sa[8], sb[8];
    const int w = tid >> 5, l = tid & 31;
    if (l == 0) { sa[w] = sc; sb[w] = sp; }
    __syncthreads();
    float tc = 0.f, tp = 0.f;
#pragma unroll
    for (int i = 0; i < 8; i++) { tc += sa[i]; tp += sb[i]; }

    const float rc = rsqrtf(tc * (1.0f / Dd) + 1e-6f);
    const float rp = rsqrtf(tp * (1.0f / Dd) + 1e-6f);

    float4* gate4 = (float4*)(g_gate + base);
    float4* co4 = (float4*)(c_out + base);
#pragma unroll
    for (int i = 0; i < 2; i++) {
        float4 g;
        g.x = tf32r(cv[i].x * rc + pv[i].x * rp);
        g.y = tf32r(cv[i].y * rc + pv[i].y * rp);
        g.z = tf32r(cv[i].z * rc + pv[i].z * rp);
        g.w = tf32r(cv[i].w * rc + pv[i].w * rp);
        gate4[tid + i * 256] = g;
        co4[tid + i * 256] = cv[i];
    }
}

// ============================================================
// K2: tf32 mma.sync GEMM with ldmatrix fragment loads.
// 128x128x32 tile, 3-stage cp.async pipeline, 2 CTAs/SM.
// grid (32, 64): x<16 -> alpha/sigmoid, x>=16 -> beta/silu. 256 threads.
// ============================================================
__global__ __launch_bounds__(256, 2)
void gemm_hmma_kernel(const float* __restrict__ ba, const float* __restrict__ bb)
{
    extern __shared__ float smem[];
    float* Asm = smem;                         // [NST][TILE_FLOATS]
    float* Bsm = smem + NST * TILE_FLOATS;     // [NST][TILE_FLOATS]

    const int tid = threadIdx.x;
    const int lane = tid & 31;
    const int wid = tid >> 5;
    const int warp_m = wid >> 2;   // 0..1
    const int warp_n = wid & 3;    // 0..3

    const int bx = blockIdx.x;     // 0..31 -> 4096 WT rows
    const int by = blockIdx.y;     // 0..63
    const int m0 = by * BM;
    const int n0g = bx * BN;       // row offset into g_WT

    const float* __restrict__ Abase = g_gate + (size_t)m0 * Dd;
    const float* __restrict__ Bbase = g_WT + (size_t)n0g * Dd;

    float acc[4][4][4];
#pragma unroll
    for (int i = 0; i < 4; i++)
#pragma unroll
        for (int j = 0; j < 4; j++)
#pragma unroll
            for (int q = 0; q < 4; q++) acc[i][j][q] = 0.f;

    const uint32_t sA0 = smem_u32(Asm);
    const uint32_t sB0 = smem_u32(Bsm);

    auto issue_stage = [&](int kt, int s) {
        const float* ag = Abase + kt * BKT;
        const float* bg = Bbase + kt * BKT;
        const uint32_t sA = sA0 + (uint32_t)(s * TILE_FLOATS) * 4;
        const uint32_t sB = sB0 + (uint32_t)(s * TILE_FLOATS) * 4;
#pragma unroll
        for (int i = 0; i < 4; i++) {
            const int chunk = tid + i * 256;      // 0..1023
            const int r = chunk >> 3;             // 0..127
            const int cc = (chunk & 7) * 4;       // 0..28
            cp_async16(sA + (uint32_t)(r * LDS_PAD + cc) * 4, ag + (size_t)r * Dd + cc);
            cp_async16(sB + (uint32_t)(r * LDS_PAD + cc) * 4, bg + (size_t)r * Dd + cc);
        }
        CP_COMMIT();
    };

    issue_stage(0, 0);
    issue_stage(1, 1);

    const int q4 = lane & 3;        // k sub-index (epilogue)
    const int r4 = lane >> 2;       // row/col sub-index (epilogue)
    const int lg = lane >> 3;       // ldmatrix tile group 0..3
    const int lr = lane & 7;        // ldmatrix row within tile

    // ldmatrix per-lane byte offsets (within a stage tile)
    // A tile mi (16x8): tiles [m0-7,k0-3],[m8-15,k0-3],[m0-7,k4-7],[m8-15,k4-7]
    uint32_t aoff[4];
#pragma unroll
    for (int mi = 0; mi < 4; mi++) {
        const int row = warp_m * 64 + mi * 16 + (lg & 1) * 8 + lr;
        const int col = (lg >> 1) * 4;
        aoff[mi] = (uint32_t)(row * LDS_PAD + col) * 4;
    }
    // B pair p (two 8x8 n-k tiles): tiles [n0-7,k0-3],[n0-7,k4-7],[n8-15,k0-3],[n8-15,k4-7]
    uint32_t boff[2];
#pragma unroll
    for (int p = 0; p < 2; p++) {
        const int row = warp_n * 32 + p * 16 + (lg >> 1) * 8 + lr;
        const int col = (lg & 1) * 4;
        boff[p] = (uint32_t)(row * LDS_PAD + col) * 4;
    }

    for (int kt = 0; kt < KTILES; kt++) {
        CP_WAIT1();
        __syncthreads();
        if (kt + 2 < KTILES) issue_stage(kt + 2, (kt + 2) % NST);

        const uint32_t sAs = sA0 + (uint32_t)((kt % NST) * TILE_FLOATS) * 4;
        const uint32_t sBs = sB0 + (uint32_t)((kt % NST) * TILE_FLOATS) * 4;

#pragma unroll
        for (int ks = 0; ks < 4; ks++) {
            const uint32_t kb = (uint32_t)(ks * 8) * 4;
            uint32_t af[4][4], bf[4][2];
#pragma unroll
            for (int mi = 0; mi < 4; mi++)
                ldsm_x4(af[mi][0], af[mi][1], af[mi][2], af[mi][3], sAs + aoff[mi] + kb);
#pragma unroll
            for (int p = 0; p < 2; p++)
                ldsm_x4(bf[2 * p][0], bf[2 * p][1], bf[2 * p + 1][0], bf[2 * p + 1][1],
                        sBs + boff[p] + kb);
#pragma unroll
            for (int mi = 0; mi < 4; mi++)
#pragma unroll
                for (int ni = 0; ni < 4; ni++)
                    mma_tf32_16n8k8(acc[mi][ni][0], acc[mi][ni][1], acc[mi][ni][2], acc[mi][ni][3],
                                    af[mi][0], af[mi][1], af[mi][2], af[mi][3],
                                    bf[ni][0], bf[ni][1]);
        }
    }

    // ---- epilogue: bias + activation, direct global stores ----
    const bool isBeta = bx >= 16;
    const float* __restrict__ bias = isBeta ? bb : ba;
    float* __restrict__ Out = isBeta ? g_betas : g_alphas;
    const int n0 = (bx & 15) * BN;

#pragma unroll
    for (int mi = 0; mi < 4; mi++) {
        const int r = m0 + warp_m * 64 + mi * 16 + r4;
#pragma unroll
        for (int ni = 0; ni < 4; ni++) {
            const int ncol = n0 + warp_n * 32 + ni * 8 + q4 * 2;
            const float b0 = bias[ncol], b1 = bias[ncol + 1];
#pragma unroll
            for (int half = 0; half < 2; half++) {
                const int rr = r + half * 8;
                const float z0 = acc[mi][ni][half * 2 + 0] + b0;
                const float z1 = acc[mi][ni][half * 2 + 1] + b1;
                const float s0 = 1.0f / (1.0f + __expf(-z0));
                const float s1 = 1.0f / (1.0f + __expf(-z1));
                float2 o2;
                o2.x = isBeta ? z0 * s0 : s0;
                o2.y = isBeta ? z1 * s1 : s1;
                *(float2*)&Out[(size_t)rr * Dd + ncol] = o2;
            }
        }
    }
}

// ============================================================
// Scan: h_t = alpha_t * h_{t-1} + x_t,  x = v*beta*sqrt(max(1-a^2,1e-6))
// float2-vectorized: each thread handles 2 adjacent d channels.
// ============================================================
__global__ __launch_bounds__(256)
void scan_phase1(const float* __restrict__ v)
{
    const int ch2 = blockIdx.y * 256 + threadIdx.x;  // float2 channel 0..2047
    const int chunk = blockIdx.x;
    const int b = ch2 >> 10;
    const int d2 = ch2 & 1023;
    size_t idx = ((size_t)b * Sq + (size_t)(chunk * TCH)) * (Dd / 2) + d2;  // float2 units

    const float2* __restrict__ A2 = (const float2*)g_alphas;
    const float2* __restrict__ B2 = (const float2*)g_betas;
    const float2* __restrict__ V2 = (const float2*)v;

    float hx = 0.f, hy = 0.f, apx = 1.f, apy = 1.f;
#pragma unroll 8
    for (int i = 0; i < TCH; i++, idx += Dd / 2) {
        const float2 a = A2[idx];
        const float2 be = B2[idx];
        const float2 vv = V2[idx];
        const float wsx = sqrtf(fmaxf(1.0f - a.x * a.x, 1e-6f));
        const float wsy = sqrtf(fmaxf(1.0f - a.y * a.y, 1e-6f));
        hx = fmaf(a.x, hx, vv.x * be.x * wsx);
        hy = fmaf(a.y, hy, vv.y * be.y * wsy);
        apx *= a.x; apy *= a.y;
    }
    const int cb = chunk * CHAN + b * 2048 + 2 * d2;
    *(float2*)&g_Hc[cb] = make_float2(hx, hy);
    *(float2*)&g_Ac[cb] = make_float2(apx, apy);
}

// Batched-load chunk-prefix scan: MLP 16 within each batch, serial FMA in regs.
__global__ __launch_bounds__(128)
void scan_phase2()
{
    const int ch = blockIdx.x * 128 + threadIdx.x;
    float carry = 0.f;
#pragma unroll
    for (int k0 = 0; k0 < NCHUNK; k0 += 8) {
        float a[8], h[8];
#pragma unroll
        for (int j = 0; j < 8; j++) {
            a[j] = g_Ac[(k0 + j) * CHAN + ch];
            h[j] = g_Hc[(k0 + j) * CHAN + ch];
        }
#pragma unroll
        for (int j = 0; j < 8; j++) {
            g_carry[(k0 + j) * CHAN + ch] = carry;
            carry = fmaf(a[j], carry, h[j]);
        }
    }
}

__global__ __launch_bounds__(256)
void scan_phase3(const float* __restrict__ v,
                 const float* __restrict__ outp,
                 const float* __restrict__ go,
                 const float* __restrict__ gv,
                 float* __restrict__ o)
{
    const int ch2 = blockIdx.y * 256 + threadIdx.x;  // float2 channel
    const int chunk = blockIdx.x;
    const int b = ch2 >> 10;
    const int d2 = ch2 & 1023;
    size_t idx = ((size_t)b * Sq + (size_t)(chunk * TCH)) * (Dd / 2) + d2;

    const float2* __restrict__ A2 = (const float2*)g_alphas;
    const float2* __restrict__ B2 = (const float2*)g_betas;
    const float2* __restrict__ V2 = (const float2*)v;
    const float2* __restrict__ O2 = (const float2*)outp;
    float2* __restrict__ o2 = (float2*)o;

    const int cb = chunk * CHAN + b * 2048 + 2 * d2;
    float2 h = *(const float2*)&g_carry[cb];
    const float2 gouts = *(const float2*)&go[2 * d2];
    const float2 gvs = *(const float2*)&gv[2 * d2];
    const size_t N2 = NTOT / 2;

#pragma unroll 8
    for (int i = 0; i < TCH; i++, idx += Dd / 2) {
        const float2 a = A2[idx];
        const float2 be = B2[idx];
        const float2 vv = V2[idx];
        const float2 op = O2[idx];
        const float wsx = sqrtf(fmaxf(1.0f - a.x * a.x, 1e-6f));
        const float wsy = sqrtf(fmaxf(1.0f - a.y * a.y, 1e-6f));
        h.x = fmaf(a.x, h.x, vv.x * be.x * wsx);
        h.y = fmaf(a.y, h.y, vv.y * be.y * wsy);
        o2[idx] = make_float2(fmaf(h.x, gvs.x, vv.x), fmaf(h.y, gvs.y, vv.y));
        o2[N2 + idx] = make_float2(fmaf(h.x, gouts.x, op.x), fmaf(h.y, gouts.y, op.y));
        o2[3 * N2 + idx] = h;
    }
}

// ============================================================
extern "C" void kernel_launch(void* const* d_in, const int* in_sizes, int n_in,
                              void* d_out, int out_size)
{
    const float* v   = (const float*)d_in[0];
    const float* out = (const float*)d_in[1];
    const float* c   = (const float*)d_in[2];
    const float* pf  = (const float*)d_in[3];
    const float* Wa  = (const float*)d_in[4];
    const float* ba  = (const float*)d_in[5];
    const float* Wb  = (const float*)d_in[6];
    const float* bb  = (const float*)d_in[7];
    const float* go  = (const float*)d_in[8];
    const float* gv  = (const float*)d_in[9];
    float* o = (float*)d_out;

    cudaFuncSetAttribute(gemm_hmma_kernel, cudaFuncAttributeMaxDynamicSharedMemorySize,
                         DSMEM_BYTES);

    // K0: transpose + tf32-round W
    dim3 tgrid(Dd / 32, Dd / 32, 2);
    transpose_w_kernel<<<tgrid, dim3(32, 8)>>>(Wa, Wb);

    // K1: gate + c passthrough
    rms_gate_kernel<<<Mrows, 256>>>(c, pf, o + 2 * NTOT);

    // K2: tensor-core (HMMA tf32 + ldmatrix) GEMM + activations
    gemm_hmma_kernel<<<dim3(32, 64), 256, DSMEM_BYTES>>>(ba, bb);

    // K3-K5: chunked scan + fused outputs (float2-vectorized)
    dim3 s1grid(NCHUNK, CHAN / 2 / 256);
    scan_phase1<<<s1grid, 256>>>(v);
    scan_phase2<<<CHAN / 128, 128>>>();
    scan_phase3<<<s1grid, 256>>>(v, out, go, gv, o);
}

// round 13
// speedup vs baseline: 1.0003x; 1.0003x over previous
#include <cuda_runtime.h>
#include <cuda_bf16.h>
#include <cstdint>

// ---------------- problem constants (B=2, S=4096, D=2048) ----------------
constexpr int Bb = 2, Sq = 4096, Dd = 2048;
constexpr int Mrows = Bb * Sq;                    // 8192 GEMM rows
constexpr size_t NTOT = (size_t)Bb * Sq * Dd;     // 16,777,216
constexpr int NCHUNK = 64, TCH = Sq / NCHUNK, CHAN = Bb * Dd;

// ---------------- GEMM tiling ----------------
constexpr int BM = 128, BN = 128, BKT = 32;       // CTA tile
constexpr int KTILES = Dd / BKT;                  // 64
constexpr int NST = 3;                            // pipeline stages
constexpr int LDS_PAD = 36;                       // floats per smem row (32 + 4 pad)
constexpr int TILE_FLOATS = 128 * LDS_PAD;        // per A or B tile
constexpr int DSMEM_BYTES = NST * 2 * TILE_FLOATS * 4;  // 110,592 B

// ---------------- scratch (device globals; allocation-free) ----------------
__device__ float g_gate[(size_t)Mrows * Dd];      // tf32-rounded gate
__device__ float g_WT[2ull * Dd * Dd];            // [4096][2048] K-major: WaT ; WbT (tf32)
__device__ float g_alphas[(size_t)Mrows * Dd];
__device__ float g_betas[(size_t)Mrows * Dd];
__device__ float g_Ac[NCHUNK * CHAN], g_Hc[NCHUNK * CHAN], g_carry[NCHUNK * CHAN];

// ================= helpers =================
__device__ __forceinline__ uint32_t smem_u32(const void* p) {
    uint32_t a;
    asm("{ .reg .u64 t; cvta.to.shared.u64 t, %1; cvt.u32.u64 %0, t; }" : "=r"(a) : "l"(p));
    return a;
}
__device__ __forceinline__ float tf32r(float x) {
    uint32_t r;
    asm("cvt.rna.tf32.f32 %0, %1;" : "=r"(r) : "f"(x));
    return __uint_as_float(r);
}
__device__ __forceinline__ void cp_async16(uint32_t saddr, const void* gaddr) {
    asm volatile("cp.async.cg.shared.global [%0], [%1], 16;" :: "r"(saddr), "l"(gaddr));
}
#define CP_COMMIT() asm volatile("cp.async.commit_group;" ::: "memory")
#define CP_WAIT1()  asm volatile("cp.async.wait_group 1;" ::: "memory")

__device__ __forceinline__ void ldsm_x4(uint32_t& r0, uint32_t& r1, uint32_t& r2, uint32_t& r3,
                                        uint32_t addr) {
    asm volatile("ldmatrix.sync.aligned.m8n8.x4.shared.b16 {%0,%1,%2,%3}, [%4];"
                 : "=r"(r0), "=r"(r1), "=r"(r2), "=r"(r3) : "r"(addr));
}

__device__ __forceinline__ void mma_tf32_16n8k8(float& d0, float& d1, float& d2, float& d3,
                                                uint32_t a0, uint32_t a1, uint32_t a2, uint32_t a3,
                                                uint32_t b0, uint32_t b1) {
    asm volatile(
        "mma.sync.aligned.m16n8k8.row.col.f32.tf32.tf32.f32 "
        "{%0,%1,%2,%3}, {%4,%5,%6,%7}, {%8,%9}, {%0,%1,%2,%3};"
        : "+f"(d0), "+f"(d1), "+f"(d2), "+f"(d3)
        : "r"(a0), "r"(a1), "r"(a2), "r"(a3), "r"(b0), "r"(b1));
}

// ============================================================
// K0: W[K,N] -> WT[N,K] with tf32 rounding. grid (64,64,2), block (32,8)
// ============================================================
__global__ __launch_bounds__(256)
void transpose_w_kernel(const float* __restrict__ Wa, const float* __restrict__ Wb)
{
    __shared__ float t[32][33];
    const int w = blockIdx.z;
    const float* __restrict__ W = w ? Wb : Wa;
    const int bn = blockIdx.x * 32;
    const int bk = blockIdx.y * 32;
    const int tx = threadIdx.x, ty = threadIdx.y;

#pragma unroll
    for (int i = ty; i < 32; i += 8)
        t[i][tx] = W[(size_t)(bk + i) * Dd + bn + tx];
    __syncthreads();
#pragma unroll
    for (int i = ty; i < 32; i += 8)
        g_WT[(size_t)(w * Dd + bn + i) * Dd + bk + tx] = tf32r(t[tx][i]);
}

// ============================================================
// K1: gate = rms_norm(c) + rms_norm(prev_fetched) (tf32-rounded), c passthrough
// ============================================================
__global__ __launch_bounds__(256)
void rms_gate_kernel(const float* __restrict__ c,
                     const float* __restrict__ pf,
                     float* __restrict__ c_out)
{
    const int row = blockIdx.x;
    const size_t base = (size_t)row * Dd;
    const int tid = threadIdx.x;

    const float4* c4 = (const float4*)(c + base);
    const float4* p4 = (const float4*)(pf + base);

    float4 cv[2], pv[2];
    float sc = 0.f, sp = 0.f;
#pragma unroll
    for (int i = 0; i < 2; i++) {
        cv[i] = c4[tid + i * 256];
        pv[i] = p4[tid + i * 256];
        sc += cv[i].x * cv[i].x + cv[i].y * cv[i].y + cv[i].z * cv[i].z + cv[i].w * cv[i].w;
        sp += pv[i].x * pv[i].x + pv[i].y * pv[i].y + pv[i].z * pv[i].z + pv[i].w * pv[i].w;
    }
#pragma unroll
    for (int o = 16; o > 0; o >>= 1) {
        sc += __shfl_xor_sync(0xFFFFFFFFu, sc, o);
        sp += __shfl_xor_sync(0xFFFFFFFFu, sp, o);
    }
    __shared__ float sa[8], sb[8];
    const int w = tid >> 5, l = tid & 31;
    if (l == 0) { sa[w] = sc; sb[w] = sp; }
    __syncthreads();
    float tc = 0.f, tp = 0.f;
#pragma unroll
    for (int i = 0; i < 8; i++) { tc += sa[i]; tp += sb[i]; }

    const float rc = rsqrtf(tc * (1.0f / Dd) + 1e-6f);
    const float rp = rsqrtf(tp * (1.0f / Dd) + 1e-6f);

    float4* gate4 = (float4*)(g_gate + base);
    float4* co4 = (float4*)(c_out + base);
#pragma unroll
    for (int i = 0; i < 2; i++) {
        float4 g;
        g.x = tf32r(cv[i].x * rc + pv[i].x * rp);
        g.y = tf32r(cv[i].y * rc + pv[i].y * rp);
        g.z = tf32r(cv[i].z * rc + pv[i].z * rp);
        g.w = tf32r(cv[i].w * rc + pv[i].w * rp);
        gate4[tid + i * 256] = g;
        co4[tid + i * 256] = cv[i];
    }
}

// ============================================================
// K2: tf32 mma.sync GEMM with ldmatrix fragment loads.
// 128x128x32 tile, 3-stage cp.async pipeline, 2 CTAs/SM.
// grid (32, 64): x<16 -> alpha/sigmoid, x>=16 -> beta/silu. 256 threads.
// ============================================================
__global__ __launch_bounds__(256, 2)
void gemm_hmma_kernel(const float* __restrict__ ba, const float* __restrict__ bb)
{
    extern __shared__ float smem[];
    float* Asm = smem;                         // [NST][TILE_FLOATS]
    float* Bsm = smem + NST * TILE_FLOATS;     // [NST][TILE_FLOATS]

    const int tid = threadIdx.x;
    const int lane = tid & 31;
    const int wid = tid >> 5;
    const int warp_m = wid >> 2;   // 0..1
    const int warp_n = wid & 3;    // 0..3

    const int bx = blockIdx.x;     // 0..31 -> 4096 WT rows
    const int by = blockIdx.y;     // 0..63
    const int m0 = by * BM;
    const int n0g = bx * BN;       // row offset into g_WT

    const float* __restrict__ Abase = g_gate + (size_t)m0 * Dd;
    const float* __restrict__ Bbase = g_WT + (size_t)n0g * Dd;

    float acc[4][4][4];
#pragma unroll
    for (int i = 0; i < 4; i++)
#pragma unroll
        for (int j = 0; j < 4; j++)
#pragma unroll
            for (int q = 0; q < 4; q++) acc[i][j][q] = 0.f;

    const uint32_t sA0 = smem_u32(Asm);
    const uint32_t sB0 = smem_u32(Bsm);

    auto issue_stage = [&](int kt, int s) {
        const float* ag = Abase + kt * BKT;
        const float* bg = Bbase + kt * BKT;
        const uint32_t sA = sA0 + (uint32_t)(s * TILE_FLOATS) * 4;
        const uint32_t sB = sB0 + (uint32_t)(s * TILE_FLOATS) * 4;
#pragma unroll
        for (int i = 0; i < 4; i++) {
            const int chunk = tid + i * 256;      // 0..1023
            const int r = chunk >> 3;             // 0..127
            const int cc = (chunk & 7) * 4;       // 0..28
            cp_async16(sA + (uint32_t)(r * LDS_PAD + cc) * 4, ag + (size_t)r * Dd + cc);
            cp_async16(sB + (uint32_t)(r * LDS_PAD + cc) * 4, bg + (size_t)r * Dd + cc);
        }
        CP_COMMIT();
    };

    issue_stage(0, 0);
    issue_stage(1, 1);

    const int q4 = lane & 3;        // k sub-index (epilogue)
    const int r4 = lane >> 2;       // row/col sub-index (epilogue)
    const int lg = lane >> 3;       // ldmatrix tile group 0..3
    const int lr = lane & 7;        // ldmatrix row within tile

    // ldmatrix per-lane byte offsets (within a stage tile)
    // A tile mi (16x8): tiles [m0-7,k0-3],[m8-15,k0-3],[m0-7,k4-7],[m8-15,k4-7]
    uint32_t aoff[4];
#pragma unroll
    for (int mi = 0; mi < 4; mi++) {
        const int row = warp_m * 64 + mi * 16 + (lg & 1) * 8 + lr;
        const int col = (lg >> 1) * 4;
        aoff[mi] = (uint32_t)(row * LDS_PAD + col) * 4;
    }
    // B pair p (two 8x8 n-k tiles): tiles [n0-7,k0-3],[n0-7,k4-7],[n8-15,k0-3],[n8-15,k4-7]
    uint32_t boff[2];
#pragma unroll
    for (int p = 0; p < 2; p++) {
        const int row = warp_n * 32 + p * 16 + (lg >> 1) * 8 + lr;
        const int col = (lg & 1) * 4;
        boff[p] = (uint32_t)(row * LDS_PAD + col) * 4;
    }

    for (int kt = 0; kt < KTILES; kt++) {
        CP_WAIT1();
        __syncthreads();
        if (kt + 2 < KTILES) issue_stage(kt + 2, (kt + 2) % NST);

        const uint32_t sAs = sA0 + (uint32_t)((kt % NST) * TILE_FLOATS) * 4;
        const uint32_t sBs = sB0 + (uint32_t)((kt % NST) * TILE_FLOATS) * 4;

#pragma unroll
        for (int ks = 0; ks < 4; ks++) {
            const uint32_t kb = (uint32_t)(ks * 8) * 4;
            uint32_t af[4][4], bf[4][2];
#pragma unroll
            for (int mi = 0; mi < 4; mi++)
                ldsm_x4(af[mi][0], af[mi][1], af[mi][2], af[mi][3], sAs + aoff[mi] + kb);
#pragma unroll
            for (int p = 0; p < 2; p++)
                ldsm_x4(bf[2 * p][0], bf[2 * p][1], bf[2 * p + 1][0], bf[2 * p + 1][1],
                        sBs + boff[p] + kb);
#pragma unroll
            for (int mi = 0; mi < 4; mi++)
#pragma unroll
                for (int ni = 0; ni < 4; ni++)
                    mma_tf32_16n8k8(acc[mi][ni][0], acc[mi][ni][1], acc[mi][ni][2], acc[mi][ni][3],
                                    af[mi][0], af[mi][1], af[mi][2], af[mi][3],
                                    bf[ni][0], bf[ni][1]);
        }
    }

    // ---- epilogue: bias + activation, direct global stores ----
    const bool isBeta = bx >= 16;
    const float* __restrict__ bias = isBeta ? bb : ba;
    float* __restrict__ Out = isBeta ? g_betas : g_alphas;
    const int n0 = (bx & 15) * BN;

#pragma unroll
    for (int mi = 0; mi < 4; mi++) {
        const int r = m0 + warp_m * 64 + mi * 16 + r4;
#pragma unroll
        for (int ni = 0; ni < 4; ni++) {
            const int ncol = n0 + warp_n * 32 + ni * 8 + q4 * 2;
            const float b0 = bias[ncol], b1 = bias[ncol + 1];
#pragma unroll
            for (int half = 0; half < 2; half++) {
                const int rr = r + half * 8;
                const float z0 = acc[mi][ni][half * 2 + 0] + b0;
                const float z1 = acc[mi][ni][half * 2 + 1] + b1;
                const float s0 = 1.0f / (1.0f + __expf(-z0));
                const float s1 = 1.0f / (1.0f + __expf(-z1));
                float2 o2;
                o2.x = isBeta ? z0 * s0 : s0;
                o2.y = isBeta ? z1 * s1 : s1;
                *(float2*)&Out[(size_t)rr * Dd + ncol] = o2;
            }
        }
    }
}

// ============================================================
// Scan: h_t = alpha_t * h_{t-1} + x_t,  x = v*beta*sqrt(max(1-a^2,1e-6))
// float2-vectorized: each thread handles 2 adjacent d channels.
// ============================================================
__global__ __launch_bounds__(256)
void scan_phase1(const float* __restrict__ v)
{
    const int ch2 = blockIdx.y * 256 + threadIdx.x;  // float2 channel 0..2047
    const int chunk = blockIdx.x;
    const int b = ch2 >> 10;
    const int d2 = ch2 & 1023;
    size_t idx = ((size_t)b * Sq + (size_t)(chunk * TCH)) * (Dd / 2) + d2;  // float2 units

    const float2* __restrict__ A2 = (const float2*)g_alphas;
    const float2* __restrict__ B2 = (const float2*)g_betas;
    const float2* __restrict__ V2 = (const float2*)v;

    float hx = 0.f, hy = 0.f, apx = 1.f, apy = 1.f;
#pragma unroll 8
    for (int i = 0; i < TCH; i++, idx += Dd / 2) {
        const float2 a = A2[idx];
        const float2 be = B2[idx];
        const float2 vv = V2[idx];
        const float wsx = sqrtf(fmaxf(1.0f - a.x * a.x, 1e-6f));
        const float wsy = sqrtf(fmaxf(1.0f - a.y * a.y, 1e-6f));
        hx = fmaf(a.x, hx, vv.x * be.x * wsx);
        hy = fmaf(a.y, hy, vv.y * be.y * wsy);
        apx *= a.x; apy *= a.y;
    }
    const int cb = chunk * CHAN + b * 2048 + 2 * d2;
    *(float2*)&g_Hc[cb] = make_float2(hx, hy);
    *(float2*)&g_Ac[cb] = make_float2(apx, apy);
}

// Batched-load chunk-prefix scan: MLP 16 within each batch, serial FMA in regs.
__global__ __launch_bounds__(128)
void scan_phase2()
{
    const int ch = blockIdx.x * 128 + threadIdx.x;
    float carry = 0.f;
#pragma unroll
    for (int k0 = 0; k0 < NCHUNK; k0 += 8) {
        float a[8], h[8];
#pragma unroll
        for (int j = 0; j < 8; j++) {
            a[j] = g_Ac[(k0 + j) * CHAN + ch];
            h[j] = g_Hc[(k0 + j) * CHAN + ch];
        }
#pragma unroll
        for (int j = 0; j < 8; j++) {
            g_carry[(k0 + j) * CHAN + ch] = carry;
            carry = fmaf(a[j], carry, h[j]);
        }
    }
}

__global__ __launch_bounds__(256)
void scan_phase3(const float* __restrict__ v,
                 const float* __restrict__ outp,
                 const float* __restrict__ go,
                 const float* __restrict__ gv,
                 float* __restrict__ o)
{
    const int ch2 = blockIdx.y * 256 + threadIdx.x;  // float2 channel
    const int chunk = blockIdx.x;
    const int b = ch2 >> 10;
    const int d2 = ch2 & 1023;
    size_t idx = ((size_t)b * Sq + (size_t)(chunk * TCH)) * (Dd / 2) + d2;

    const float2* __restrict__ A2 = (const float2*)g_alphas;
    const float2* __restrict__ B2 = (const float2*)g_betas;
    const float2* __restrict__ V2 = (const float2*)v;
    const float2* __restrict__ O2 = (const float2*)outp;
    float2* __restrict__ o2 = (float2*)o;

    const int cb = chunk * CHAN + b * 2048 + 2 * d2;
    float2 h = *(const float2*)&g_carry[cb];
    const float2 gouts = *(const float2*)&go[2 * d2];
    const float2 gvs = *(const float2*)&gv[2 * d2];
    const size_t N2 = NTOT / 2;

#pragma unroll 8
    for (int i = 0; i < TCH; i++, idx += Dd / 2) {
        const float2 a = A2[idx];
        const float2 be = B2[idx];
        const float2 vv = V2[idx];
        const float2 op = O2[idx];
        const float wsx = sqrtf(fmaxf(1.0f - a.x * a.x, 1e-6f));
        const float wsy = sqrtf(fmaxf(1.0f - a.y * a.y, 1e-6f));
        h.x = fmaf(a.x, h.x, vv.x * be.x * wsx);
        h.y = fmaf(a.y, h.y, vv.y * be.y * wsy);
        o2[idx] = make_float2(fmaf(h.x, gvs.x, vv.x), fmaf(h.y, gvs.y, vv.y));
        o2[N2 + idx] = make_float2(fmaf(h.x, gouts.x, op.x), fmaf(h.y, gouts.y, op.y));
        o2[3 * N2 + idx] = h;
    }
}

// ============================================================
extern "C" void kernel_launch(void* const* d_in, const int* in_sizes, int n_in,
                              void* d_out, int out_size)
{
    const float* v   = (const float*)d_in[0];
    const float* out = (const float*)d_in[1];
    const float* c   = (const float*)d_in[2];
    const float* pf  = (const float*)d_in[3];
    const float* Wa  = (const float*)d_in[4];
    const float* ba  = (const float*)d_in[5];
    const float* Wb  = (const float*)d_in[6];
    const float* bb  = (const float*)d_in[7];
    const float* go  = (const float*)d_in[8];
    const float* gv  = (const float*)d_in[9];
    float* o = (float*)d_out;

    cudaFuncSetAttribute(gemm_hmma_kernel, cudaFuncAttributeMaxDynamicSharedMemorySize,
                         DSMEM_BYTES);

    // K0: transpose + tf32-round W
    dim3 tgrid(Dd / 32, Dd / 32, 2);
    transpose_w_kernel<<<tgrid, dim3(32, 8)>>>(Wa, Wb);

    // K1: gate + c passthrough
    rms_gate_kernel<<<Mrows, 256>>>(c, pf, o + 2 * NTOT);

    // K2: tensor-core (HMMA tf32 + ldmatrix) GEMM + activations
    gemm_hmma_kernel<<<dim3(32, 64), 256, DSMEM_BYTES>>>(ba, bb);

    // K3-K5: chunked scan + fused outputs (float2-vectorized)
    dim3 s1grid(NCHUNK, CHAN / 2 / 256);
    scan_phase1<<<s1grid, 256>>>(v);
    scan_phase2<<<CHAN / 128, 128>>>();
    scan_phase3<<<s1grid, 256>>>(v, out, go, gv, o);
}

// round 14
// speedup vs baseline: 1.0014x; 1.0011x over previous
#include <cuda_runtime.h>
#include <cuda_bf16.h>
#include <cstdint>

// ---------------- problem constants (B=2, S=4096, D=2048) ----------------
constexpr int Bb = 2, Sq = 4096, Dd = 2048;
constexpr int Mrows = Bb * Sq;                    // 8192 GEMM rows
constexpr size_t NTOT = (size_t)Bb * Sq * Dd;     // 16,777,216
constexpr int NCHUNK = 64, TCH = Sq / NCHUNK, CHAN = Bb * Dd;

// ---------------- GEMM tiling ----------------
constexpr int BM = 128, BN = 128, BKT = 32;       // CTA tile
constexpr int KTILES = Dd / BKT;                  // 64
constexpr int NST = 3;                            // pipeline stages
constexpr int LDS_PAD = 36;                       // floats per smem row (32 + 4 pad)
constexpr int TILE_FLOATS = 128 * LDS_PAD;        // per A or B tile
constexpr int DSMEM_BYTES = NST * 2 * TILE_FLOATS * 4;  // 110,592 B

// ---------------- scratch (device globals; allocation-free) ----------------
__device__ float g_gate[(size_t)Mrows * Dd];      // tf32-rounded gate
__device__ float g_WT[2ull * Dd * Dd];            // [4096][2048] K-major: WaT ; WbT (tf32)
__device__ float g_alphas[(size_t)Mrows * Dd];
__device__ float g_betas[(size_t)Mrows * Dd];
__device__ float g_Ac[NCHUNK * CHAN], g_Hc[NCHUNK * CHAN], g_carry[NCHUNK * CHAN];

// ================= helpers =================
__device__ __forceinline__ uint32_t smem_u32(const void* p) {
    uint32_t a;
    asm("{ .reg .u64 t; cvta.to.shared.u64 t, %1; cvt.u32.u64 %0, t; }" : "=r"(a) : "l"(p));
    return a;
}
__device__ __forceinline__ float tf32r(float x) {
    uint32_t r;
    asm("cvt.rna.tf32.f32 %0, %1;" : "=r"(r) : "f"(x));
    return __uint_as_float(r);
}
__device__ __forceinline__ void cp_async16(uint32_t saddr, const void* gaddr) {
    asm volatile("cp.async.cg.shared.global [%0], [%1], 16;" :: "r"(saddr), "l"(gaddr));
}
#define CP_COMMIT() asm volatile("cp.async.commit_group;" ::: "memory")
#define CP_WAIT1()  asm volatile("cp.async.wait_group 1;" ::: "memory")

__device__ __forceinline__ void ldsm_x4(uint32_t& r0, uint32_t& r1, uint32_t& r2, uint32_t& r3,
                                        uint32_t addr) {
    asm volatile("ldmatrix.sync.aligned.m8n8.x4.shared.b16 {%0,%1,%2,%3}, [%4];"
                 : "=r"(r0), "=r"(r1), "=r"(r2), "=r"(r3) : "r"(addr));
}

__device__ __forceinline__ void mma_tf32_16n8k8(float& d0, float& d1, float& d2, float& d3,
                                                uint32_t a0, uint32_t a1, uint32_t a2, uint32_t a3,
                                                uint32_t b0, uint32_t b1) {
    asm volatile(
        "mma.sync.aligned.m16n8k8.row.col.f32.tf32.tf32.f32 "
        "{%0,%1,%2,%3}, {%4,%5,%6,%7}, {%8,%9}, {%0,%1,%2,%3};"
        : "+f"(d0), "+f"(d1), "+f"(d2), "+f"(d3)
        : "r"(a0), "r"(a1), "r"(a2), "r"(a3), "r"(b0), "r"(b1));
}

// ============================================================
// K0: W[K,N] -> WT[N,K] with tf32 rounding. grid (64,64,2), block (32,8)
// ============================================================
__global__ __launch_bounds__(256)
void transpose_w_kernel(const float* __restrict__ Wa, const float* __restrict__ Wb)
{
    __shared__ float t[32][33];
    const int w = blockIdx.z;
    const float* __restrict__ W = w ? Wb : Wa;
    const int bn = blockIdx.x * 32;
    const int bk = blockIdx.y * 32;
    const int tx = threadIdx.x, ty = threadIdx.y;

#pragma unroll
    for (int i = ty; i < 32; i += 8)
        t[i][tx] = W[(size_t)(bk + i) * Dd + bn + tx];
    __syncthreads();
#pragma unroll
    for (int i = ty; i < 32; i += 8)
        g_WT[(size_t)(w * Dd + bn + i) * Dd + bk + tx] = tf32r(t[tx][i]);
}

// ============================================================
// K1: gate = rms_norm(c) + rms_norm(prev_fetched) (tf32-rounded), c passthrough
// ============================================================
__global__ __launch_bounds__(256)
void rms_gate_kernel(const float* __restrict__ c,
                     const float* __restrict__ pf,
                     float* __restrict__ c_out)
{
    const int row = blockIdx.x;
    const size_t base = (size_t)row * Dd;
    const int tid = threadIdx.x;

    const float4* c4 = (const float4*)(c + base);
    const float4* p4 = (const float4*)(pf + base);

    float4 cv[2], pv[2];
    float sc = 0.f, sp = 0.f;
#pragma unroll
    for (int i = 0; i < 2; i++) {
        cv[i] = c4[tid + i * 256];
        pv[i] = p4[tid + i * 256];
        sc += cv[i].x * cv[i].x + cv[i].y * cv[i].y + cv[i].z * cv[i].z + cv[i].w * cv[i].w;
        sp += pv[i].x * pv[i].x + pv[i].y * pv[i].y + pv[i].z * pv[i].z + pv[i].w * pv[i].w;
    }
#pragma unroll
    for (int o = 16; o > 0; o >>= 1) {
        sc += __shfl_xor_sync(0xFFFFFFFFu, sc, o);
        sp += __shfl_xor_sync(0xFFFFFFFFu, sp, o);
    }
    __shared__ float sa[8], sb[8];
    const int w = tid >> 5, l = tid & 31;
    if (l == 0) { sa[w] = sc; sb[w] = sp; }
    __syncthreads();
    float tc = 0.f, tp = 0.f;
#pragma unroll
    for (int i = 0; i < 8; i++) { tc += sa[i]; tp += sb[i]; }

    const float rc = rsqrtf(tc * (1.0f / Dd) + 1e-6f);
    const float rp = rsqrtf(tp * (1.0f / Dd) + 1e-6f);

    float4* gate4 = (float4*)(g_gate + base);
    float4* co4 = (float4*)(c_out + base);
#pragma unroll
    for (int i = 0; i < 2; i++) {
        float4 g;
        g.x = tf32r(cv[i].x * rc + pv[i].x * rp);
        g.y = tf32r(cv[i].y * rc + pv[i].y * rp);
        g.z = tf32r(cv[i].z * rc + pv[i].z * rp);
        g.w = tf32r(cv[i].w * rc + pv[i].w * rp);
        gate4[tid + i * 256] = g;
        co4[tid + i * 256] = cv[i];
    }
}

// ============================================================
// K2: tf32 mma.sync GEMM with ldmatrix fragment loads.
// 128x128x32 tile, 3-stage cp.async pipeline, 2 CTAs/SM.
// grid (32, 64): x<16 -> alpha/sigmoid, x>=16 -> beta/silu. 256 threads.
// ============================================================
__global__ __launch_bounds__(256, 2)
void gemm_hmma_kernel(const float* __restrict__ ba, const float* __restrict__ bb)
{
    extern __shared__ float smem[];
    float* Asm = smem;                         // [NST][TILE_FLOATS]
    float* Bsm = smem + NST * TILE_FLOATS;     // [NST][TILE_FLOATS]

    const int tid = threadIdx.x;
    const int lane = tid & 31;
    const int wid = tid >> 5;
    const int warp_m = wid >> 2;   // 0..1
    const int warp_n = wid & 3;    // 0..3

    const int bx = blockIdx.x;     // 0..31 -> 4096 WT rows
    const int by = blockIdx.y;     // 0..63
    const int m0 = by * BM;
    const int n0g = bx * BN;       // row offset into g_WT

    const float* __restrict__ Abase = g_gate + (size_t)m0 * Dd;
    const float* __restrict__ Bbase = g_WT + (size_t)n0g * Dd;

    float acc[4][4][4];
#pragma unroll
    for (int i = 0; i < 4; i++)
#pragma unroll
        for (int j = 0; j < 4; j++)
#pragma unroll
            for (int q = 0; q < 4; q++) acc[i][j][q] = 0.f;

    const uint32_t sA0 = smem_u32(Asm);
    const uint32_t sB0 = smem_u32(Bsm);

    auto issue_stage = [&](int kt, int s) {
        const float* ag = Abase + kt * BKT;
        const float* bg = Bbase + kt * BKT;
        const uint32_t sA = sA0 + (uint32_t)(s * TILE_FLOATS) * 4;
        const uint32_t sB = sB0 + (uint32_t)(s * TILE_FLOATS) * 4;
#pragma unroll
        for (int i = 0; i < 4; i++) {
            const int chunk = tid + i * 256;      // 0..1023
            const int r = chunk >> 3;             // 0..127
            const int cc = (chunk & 7) * 4;       // 0..28
            cp_async16(sA + (uint32_t)(r * LDS_PAD + cc) * 4, ag + (size_t)r * Dd + cc);
            cp_async16(sB + (uint32_t)(r * LDS_PAD + cc) * 4, bg + (size_t)r * Dd + cc);
        }
        CP_COMMIT();
    };

    issue_stage(0, 0);
    issue_stage(1, 1);

    const int q4 = lane & 3;        // k sub-index (epilogue)
    const int r4 = lane >> 2;       // row/col sub-index (epilogue)
    const int lg = lane >> 3;       // ldmatrix tile group 0..3
    const int lr = lane & 7;        // ldmatrix row within tile

    // ldmatrix per-lane byte offsets (within a stage tile)
    // A tile mi (16x8): tiles [m0-7,k0-3],[m8-15,k0-3],[m0-7,k4-7],[m8-15,k4-7]
    uint32_t aoff[4];
#pragma unroll
    for (int mi = 0; mi < 4; mi++) {
        const int row = warp_m * 64 + mi * 16 + (lg & 1) * 8 + lr;
        const int col = (lg >> 1) * 4;
        aoff[mi] = (uint32_t)(row * LDS_PAD + col) * 4;
    }
    // B pair p (two 8x8 n-k tiles): tiles [n0-7,k0-3],[n0-7,k4-7],[n8-15,k0-3],[n8-15,k4-7]
    uint32_t boff[2];
#pragma unroll
    for (int p = 0; p < 2; p++) {
        const int row = warp_n * 32 + p * 16 + (lg >> 1) * 8 + lr;
        const int col = (lg & 1) * 4;
        boff[p] = (uint32_t)(row * LDS_PAD + col) * 4;
    }

    for (int kt = 0; kt < KTILES; kt++) {
        CP_WAIT1();
        __syncthreads();
        if (kt + 2 < KTILES) issue_stage(kt + 2, (kt + 2) % NST);

        const uint32_t sAs = sA0 + (uint32_t)((kt % NST) * TILE_FLOATS) * 4;
        const uint32_t sBs = sB0 + (uint32_t)((kt % NST) * TILE_FLOATS) * 4;

#pragma unroll
        for (int ks = 0; ks < 4; ks++) {
            const uint32_t kb = (uint32_t)(ks * 8) * 4;
            uint32_t af[4][4], bf[4][2];
#pragma unroll
            for (int mi = 0; mi < 4; mi++)
                ldsm_x4(af[mi][0], af[mi][1], af[mi][2], af[mi][3], sAs + aoff[mi] + kb);
#pragma unroll
            for (int p = 0; p < 2; p++)
                ldsm_x4(bf[2 * p][0], bf[2 * p][1], bf[2 * p + 1][0], bf[2 * p + 1][1],
                        sBs + boff[p] + kb);
#pragma unroll
            for (int mi = 0; mi < 4; mi++)
#pragma unroll
                for (int ni = 0; ni < 4; ni++)
                    mma_tf32_16n8k8(acc[mi][ni][0], acc[mi][ni][1], acc[mi][ni][2], acc[mi][ni][3],
                                    af[mi][0], af[mi][1], af[mi][2], af[mi][3],
                                    bf[ni][0], bf[ni][1]);
        }
    }

    // ---- epilogue: bias + activation, direct global stores ----
    const bool isBeta = bx >= 16;
    const float* __restrict__ bias = isBeta ? bb : ba;
    float* __restrict__ Out = isBeta ? g_betas : g_alphas;
    const int n0 = (bx & 15) * BN;

#pragma unroll
    for (int mi = 0; mi < 4; mi++) {
        const int r = m0 + warp_m * 64 + mi * 16 + r4;
#pragma unroll
        for (int ni = 0; ni < 4; ni++) {
            const int ncol = n0 + warp_n * 32 + ni * 8 + q4 * 2;
            const float b0 = bias[ncol], b1 = bias[ncol + 1];
#pragma unroll
            for (int half = 0; half < 2; half++) {
                const int rr = r + half * 8;
                const float z0 = acc[mi][ni][half * 2 + 0] + b0;
                const float z1 = acc[mi][ni][half * 2 + 1] + b1;
                const float s0 = 1.0f / (1.0f + __expf(-z0));
                const float s1 = 1.0f / (1.0f + __expf(-z1));
                float2 o2;
                o2.x = isBeta ? z0 * s0 : s0;
                o2.y = isBeta ? z1 * s1 : s1;
                *(float2*)&Out[(size_t)rr * Dd + ncol] = o2;
            }
        }
    }
}

// ============================================================
// Scan: h_t = alpha_t * h_{t-1} + x_t,  x = v*beta*sqrt(max(1-a^2,1e-6))
// float2-vectorized: each thread handles 2 adjacent d channels.
// ============================================================
__global__ __launch_bounds__(256)
void scan_phase1(const float* __restrict__ v)
{
    const int ch2 = blockIdx.y * 256 + threadIdx.x;  // float2 channel 0..2047
    const int chunk = blockIdx.x;
    const int b = ch2 >> 10;
    const int d2 = ch2 & 1023;
    size_t idx = ((size_t)b * Sq + (size_t)(chunk * TCH)) * (Dd / 2) + d2;  // float2 units

    const float2* __restrict__ A2 = (const float2*)g_alphas;
    const float2* __restrict__ B2 = (const float2*)g_betas;
    const float2* __restrict__ V2 = (const float2*)v;

    float hx = 0.f, hy = 0.f, apx = 1.f, apy = 1.f;
#pragma unroll 8
    for (int i = 0; i < TCH; i++, idx += Dd / 2) {
        const float2 a = A2[idx];
        const float2 be = B2[idx];
        const float2 vv = V2[idx];
        const float wsx = sqrtf(fmaxf(1.0f - a.x * a.x, 1e-6f));
        const float wsy = sqrtf(fmaxf(1.0f - a.y * a.y, 1e-6f));
        hx = fmaf(a.x, hx, vv.x * be.x * wsx);
        hy = fmaf(a.y, hy, vv.y * be.y * wsy);
        apx *= a.x; apy *= a.y;
    }
    const int cb = chunk * CHAN + b * 2048 + 2 * d2;
    *(float2*)&g_Hc[cb] = make_float2(hx, hy);
    *(float2*)&g_Ac[cb] = make_float2(apx, apy);
}

// Batched-load chunk-prefix scan: MLP 16 within each batch, serial FMA in regs.
__global__ __launch_bounds__(128)
void scan_phase2()
{
    const int ch = blockIdx.x * 128 + threadIdx.x;
    float carry = 0.f;
#pragma unroll
    for (int k0 = 0; k0 < NCHUNK; k0 += 8) {
        float a[8], h[8];
#pragma unroll
        for (int j = 0; j < 8; j++) {
            a[j] = g_Ac[(k0 + j) * CHAN + ch];
            h[j] = g_Hc[(k0 + j) * CHAN + ch];
        }
#pragma unroll
        for (int j = 0; j < 8; j++) {
            g_carry[(k0 + j) * CHAN + ch] = carry;
            carry = fmaf(a[j], carry, h[j]);
        }
    }
}

__global__ __launch_bounds__(256)
void scan_phase3(const float* __restrict__ v,
                 const float* __restrict__ outp,
                 const float* __restrict__ go,
                 const float* __restrict__ gv,
                 float* __restrict__ o)
{
    const int ch2 = blockIdx.y * 256 + threadIdx.x;  // float2 channel
    const int chunk = blockIdx.x;
    const int b = ch2 >> 10;
    const int d2 = ch2 & 1023;
    size_t idx = ((size_t)b * Sq + (size_t)(chunk * TCH)) * (Dd / 2) + d2;

    const float2* __restrict__ A2 = (const float2*)g_alphas;
    const float2* __restrict__ B2 = (const float2*)g_betas;
    const float2* __restrict__ V2 = (const float2*)v;
    const float2* __restrict__ O2 = (const float2*)outp;
    float2* __restrict__ o2 = (float2*)o;

    const int cb = chunk * CHAN + b * 2048 + 2 * d2;
    float2 h = *(const float2*)&g_carry[cb];
    const float2 gouts = *(const float2*)&go[2 * d2];
    const float2 gvs = *(const float2*)&gv[2 * d2];
    const size_t N2 = NTOT / 2;

#pragma unroll 8
    for (int i = 0; i < TCH; i++, idx += Dd / 2) {
        const float2 a = A2[idx];
        const float2 be = B2[idx];
        const float2 vv = V2[idx];
        const float2 op = O2[idx];
        const float wsx = sqrtf(fmaxf(1.0f - a.x * a.x, 1e-6f));
        const float wsy = sqrtf(fmaxf(1.0f - a.y * a.y, 1e-6f));
        h.x = fmaf(a.x, h.x, vv.x * be.x * wsx);
        h.y = fmaf(a.y, h.y, vv.y * be.y * wsy);
        o2[idx] = make_float2(fmaf(h.x, gvs.x, vv.x), fmaf(h.y, gvs.y, vv.y));
        o2[N2 + idx] = make_float2(fmaf(h.x, gouts.x, op.x), fmaf(h.y, gouts.y, op.y));
        o2[3 * N2 + idx] = h;
    }
}

// ============================================================
extern "C" void kernel_launch(void* const* d_in, const int* in_sizes, int n_in,
                              void* d_out, int out_size)
{
    const float* v   = (const float*)d_in[0];
    const float* out = (const float*)d_in[1];
    const float* c   = (const float*)d_in[2];
    const float* pf  = (const float*)d_in[3];
    const float* Wa  = (const float*)d_in[4];
    const float* ba  = (const float*)d_in[5];
    const float* Wb  = (const float*)d_in[6];
    const float* bb  = (const float*)d_in[7];
    const float* go  = (const float*)d_in[8];
    const float* gv  = (const float*)d_in[9];
    float* o = (float*)d_out;

    cudaFuncSetAttribute(gemm_hmma_kernel, cudaFuncAttributeMaxDynamicSharedMemorySize,
                         DSMEM_BYTES);

    // K0: transpose + tf32-round W
    dim3 tgrid(Dd / 32, Dd / 32, 2);
    transpose_w_kernel<<<tgrid, dim3(32, 8)>>>(Wa, Wb);

    // K1: gate + c passthrough
    rms_gate_kernel<<<Mrows, 256>>>(c, pf, o + 2 * NTOT);

    // K2: tensor-core (HMMA tf32 + ldmatrix) GEMM + activations
    gemm_hmma_kernel<<<dim3(32, 64), 256, DSMEM_BYTES>>>(ba, bb);

    // K3-K5: chunked scan + fused outputs (float2-vectorized)
    dim3 s1grid(NCHUNK, CHAN / 2 / 256);
    scan_phase1<<<s1grid, 256>>>(v);
    scan_phase2<<<CHAN / 128, 128>>>();
    scan_phase3<<<s1grid, 256>>>(v, out, go, gv, o);
}